// round 1
// baseline (speedup 1.0000x reference)
#include <cuda_runtime.h>

#define BN   16
#define CN   80
#define HN   128
#define WN   128
#define HWN  (HN*WN)
#define NPLANES (BN*CN)
#define TOPK 100
#define PCAP 8192          // max candidates kept per plane (strict 3x3 maxima bound is 4356)
#define NB1  2048          // histogram bins

// Scratch (device globals: allocation-free contract)
__device__ unsigned long long g_cand[NPLANES][PCAP];   // packed (valbits<<32)|~idx
__device__ int g_pcnt[NPLANES];
__device__ int g_hist[BN][NB1];

__device__ __forceinline__ int bin1f(float v){
    int b = (int)(v * 2048.0f);
    return b < 0 ? 0 : (b > NB1-1 ? NB1-1 : b);
}
__device__ __forceinline__ int bin2f(float v, int b1){
    float f = v * 2048.0f - (float)b1;
    int b = (int)(f * 2048.0f);
    return b < 0 ? 0 : (b > NB1-1 ? NB1-1 : b);
}

__global__ void zero_kernel(){
    int tid = blockIdx.x*blockDim.x + threadIdx.x;
    int stride = gridDim.x*blockDim.x;
    for (int i = tid; i < NPLANES; i += stride) g_pcnt[i] = 0;
    for (int i = tid; i < BN*NB1;  i += stride) ((int*)g_hist)[i] = 0;
}

// One block per (batch,channel) plane. Plane staged in dynamic shared (64KB).
// No __syncthreads in the hot loop: candidates go to a per-plane slice with
// one warp-level atomic per iteration.
extern __shared__ float s_plane[];
__global__ __launch_bounds__(256) void nms_kernel(const float* __restrict__ hm){
    __shared__ int shist[NB1];
    const int plane = blockIdx.x;
    const int b  = plane / CN;
    const int ch = plane % CN;

    const float4* p4 = (const float4*)(hm + (size_t)plane * HWN);
    float4* s4 = (float4*)s_plane;
    for (int i = threadIdx.x; i < NB1; i += 256) shist[i] = 0;
    #pragma unroll 4
    for (int i = threadIdx.x; i < HWN/4; i += 256) s4[i] = p4[i];
    __syncthreads();

    const int lane = threadIdx.x & 31;
    const unsigned lmask = (1u << lane) - 1u;
    unsigned long long* slice = g_cand[plane];

    #pragma unroll 1
    for (int it = 0; it < HWN/256; ++it){
        int pix = it*256 + threadIdx.x;
        int y = pix >> 7, x = pix & (WN-1);
        float v = s_plane[pix];
        bool keep = true;
        bool hasL = x > 0, hasR = x < WN-1, hasU = y > 0, hasD = y < HN-1;
        if (hasU){
            const float* r = s_plane + (y-1)*WN;
            if (hasL && v < r[x-1]) keep = false;
            if (v < r[x])           keep = false;
            if (hasR && v < r[x+1]) keep = false;
        }
        {
            const float* r = s_plane + y*WN;
            if (hasL && v < r[x-1]) keep = false;
            if (hasR && v < r[x+1]) keep = false;
        }
        if (hasD){
            const float* r = s_plane + (y+1)*WN;
            if (hasL && v < r[x-1]) keep = false;
            if (v < r[x])           keep = false;
            if (hasR && v < r[x+1]) keep = false;
        }
        if (keep) atomicAdd(&shist[bin1f(v)], 1);

        unsigned bal = __ballot_sync(0xffffffffu, keep);
        int wcnt = __popc(bal);
        int pre  = __popc(bal & lmask);
        int wb = 0;
        if (lane == 0 && wcnt) wb = atomicAdd(&g_pcnt[plane], wcnt);
        wb = __shfl_sync(0xffffffffu, wb, 0);
        if (keep){
            int pos = wb + pre;
            if (pos < PCAP){
                unsigned vb  = __float_as_uint(v);
                unsigned idx = (unsigned)(ch*HWN + pix);
                slice[pos] = ((unsigned long long)vb << 32) | (unsigned)(~idx);
            }
        }
    }
    __syncthreads();
    for (int i = threadIdx.x; i < NB1; i += 256){
        int c = shist[i];
        if (c) atomicAdd(&g_hist[b][i], c);
    }
}

// One block per batch: 2-level histogram select -> collect -> bitonic sort -> decode.
__global__ __launch_bounds__(1024) void select_kernel(const float* __restrict__ offset,
                                                      const float* __restrict__ wh,
                                                      float* __restrict__ out){
    const int b = blockIdx.x;
    __shared__ int hist2[NB1];
    __shared__ unsigned long long cand[1024];
    __shared__ int sCollect, sB1, sR1, sB2;

    for (int i = threadIdx.x; i < NB1; i += 1024) hist2[i] = 0;
    if (threadIdx.x == 0){
        int acc = 0, bsel = 0, r = TOPK;
        for (int i = NB1-1; i >= 0; --i){
            int c = g_hist[b][i];
            if (acc + c >= TOPK){ bsel = i; r = TOPK - acc; break; }
            acc += c;
        }
        sB1 = bsel; sR1 = r; sCollect = 0;
    }
    __syncthreads();
    const int b1 = sB1, r1 = sR1;

    // level-2 histogram over candidates in bin b1
    for (int p = 0; p < CN; ++p){
        int cnt = g_pcnt[b*CN + p]; if (cnt > PCAP) cnt = PCAP;
        const unsigned long long* src = g_cand[b*CN + p];
        for (int i = threadIdx.x; i < cnt; i += 1024){
            float v = __uint_as_float((unsigned)(src[i] >> 32));
            if (bin1f(v) == b1) atomicAdd(&hist2[bin2f(v, b1)], 1);
        }
    }
    __syncthreads();
    if (threadIdx.x == 0){
        int acc = 0, bsel = 0;
        for (int i = NB1-1; i >= 0; --i){
            int c = hist2[i];
            if (acc + c >= r1){ bsel = i; break; }
            acc += c;
        }
        sB2 = bsel;
    }
    __syncthreads();
    const int b2 = sB2;

    // collect survivors (>= threshold)
    for (int p = 0; p < CN; ++p){
        int cnt = g_pcnt[b*CN + p]; if (cnt > PCAP) cnt = PCAP;
        const unsigned long long* src = g_cand[b*CN + p];
        for (int i = threadIdx.x; i < cnt; i += 1024){
            unsigned long long kk = src[i];
            float v = __uint_as_float((unsigned)(kk >> 32));
            int bb1 = bin1f(v);
            bool take = (bb1 > b1) || (bb1 == b1 && bin2f(v, b1) >= b2);
            if (take){
                int pos = atomicAdd(&sCollect, 1);
                if (pos < 1024) cand[pos] = kk;
            }
        }
    }
    __syncthreads();
    int m = sCollect; if (m > 1024) m = 1024;
    if ((int)threadIdx.x >= m) cand[threadIdx.x] = 0ull;
    __syncthreads();

    // bitonic sort, descending (key = valbits desc, then ~idx desc = idx asc)
    for (int ksz = 2; ksz <= 1024; ksz <<= 1){
        for (int j = ksz >> 1; j > 0; j >>= 1){
            int i = threadIdx.x;
            int ixj = i ^ j;
            if (ixj > i){
                unsigned long long a = cand[i], c = cand[ixj];
                bool descBlock = ((i & ksz) == 0);
                bool doswap = descBlock ? (a < c) : (a > c);
                if (doswap){ cand[i] = c; cand[ixj] = a; }
            }
            __syncthreads();
        }
    }

    if (threadIdx.x < TOPK){
        int j = threadIdx.x;
        unsigned long long kk = cand[j];
        unsigned vb = (unsigned)(kk >> 32);
        int idx = (int)(~(unsigned)kk);
        float score = __uint_as_float(vb);
        int chn = idx / HWN;
        int spatial = idx - chn*HWN;
        int ys = spatial >> 7, xs = spatial & (WN-1);
        const float* offb = offset + (size_t)b * 2 * HWN;
        const float* whb  = wh     + (size_t)b * 2 * HWN;
        float ox = offb[spatial], oy = offb[HWN + spatial];
        float ww = whb[spatial],  hh = whb[HWN + spatial];
        float cx = (float)xs + ox, cy = (float)ys + oy;
        float hw2 = ww * 0.5f, hh2 = hh * 0.5f;

        float* out_ids = out;                 // (B,100,1)
        float* out_sc  = out + BN*TOPK;       // (B,100,1)
        float* out_bb  = out + 2*BN*TOPK;     // (B,100,4)
        out_ids[b*TOPK + j] = (float)chn;
        out_sc [b*TOPK + j] = score;
        float* bbp = out_bb + (size_t)(b*TOPK + j)*4;
        bbp[0] = (cx - hw2)*4.0f;
        bbp[1] = (cy - hh2)*4.0f;
        bbp[2] = (cx + hw2)*4.0f;
        bbp[3] = (cy + hh2)*4.0f;
    }
}

extern "C" void kernel_launch(void* const* d_in, const int* in_sizes, int n_in,
                              void* d_out, int out_size){
    const float* hm     = (const float*)d_in[0];
    const float* offset = (const float*)d_in[1];
    const float* wh     = (const float*)d_in[2];
    float* out = (float*)d_out;

    cudaFuncSetAttribute(nms_kernel, cudaFuncAttributeMaxDynamicSharedMemorySize,
                         HWN * (int)sizeof(float));

    zero_kernel<<<32, 1024>>>();
    nms_kernel<<<NPLANES, 256, HWN * sizeof(float)>>>(hm);
    select_kernel<<<BN, 1024>>>(offset, wh, out);
}

// round 2
// speedup vs baseline: 1.4142x; 1.4142x over previous
#include <cuda_runtime.h>

#define BN   16
#define CN   80
#define HN   128
#define WN   128
#define HWN  (HN*WN)
#define NPLANES (BN*CN)
#define TOPK 100
#define PCAP 8192          // per-plane candidate cap (expected ~1820)
#define NB1  2048          // histogram bins
#define SCAP 2048          // survivor cap per batch (expected ~640)

// Scratch (device globals: allocation-free contract)
__device__ unsigned long long g_cand[NPLANES][PCAP];   // packed (valbits<<32)|~idx
__device__ int g_pcnt[NPLANES];

__device__ __forceinline__ int bin1f(float v){
    int b = (int)(v * 2048.0f);
    return b < 0 ? 0 : (b > NB1-1 ? NB1-1 : b);
}

// One block per (batch,channel) plane. Plane staged in 64KB dynamic shared.
// Candidate count kept in SHARED (single store to global at exit -> no zeroing pass).
extern __shared__ float s_plane[];
__global__ __launch_bounds__(256) void nms_kernel(const float* __restrict__ hm){
    __shared__ int scnt;
    const int plane = blockIdx.x;
    const int ch = plane % CN;
    if (threadIdx.x == 0) scnt = 0;

    const float4* p4 = (const float4*)(hm + (size_t)plane * HWN);
    float4* s4 = (float4*)s_plane;
    #pragma unroll 4
    for (int i = threadIdx.x; i < HWN/4; i += 256) s4[i] = p4[i];
    __syncthreads();

    const int lane = threadIdx.x & 31;
    const unsigned lmask = (1u << lane) - 1u;
    unsigned long long* slice = g_cand[plane];

    #pragma unroll 1
    for (int it = 0; it < HWN/256; ++it){
        int pix = it*256 + threadIdx.x;
        int y = pix >> 7, x = pix & (WN-1);
        float v = s_plane[pix];
        bool keep = true;
        bool hasL = x > 0, hasR = x < WN-1, hasU = y > 0, hasD = y < HN-1;
        if (hasU){
            const float* r = s_plane + (y-1)*WN;
            if (hasL && v < r[x-1]) keep = false;
            if (v < r[x])           keep = false;
            if (hasR && v < r[x+1]) keep = false;
        }
        {
            const float* r = s_plane + y*WN;
            if (hasL && v < r[x-1]) keep = false;
            if (hasR && v < r[x+1]) keep = false;
        }
        if (hasD){
            const float* r = s_plane + (y+1)*WN;
            if (hasL && v < r[x-1]) keep = false;
            if (v < r[x])           keep = false;
            if (hasR && v < r[x+1]) keep = false;
        }

        unsigned bal = __ballot_sync(0xffffffffu, keep);
        int wb = 0;
        if (lane == 0 && bal) wb = atomicAdd(&scnt, __popc(bal));
        wb = __shfl_sync(0xffffffffu, wb, 0);
        if (keep){
            int pos = wb + __popc(bal & lmask);
            if (pos < PCAP){
                unsigned vb  = __float_as_uint(v);
                unsigned idx = (unsigned)(ch*HWN + pix);
                slice[pos] = ((unsigned long long)vb << 32) | (unsigned)(~idx);
            }
        }
    }
    __syncthreads();
    if (threadIdx.x == 0) g_pcnt[plane] = (scnt > PCAP) ? PCAP : scnt;
}

// One block per batch: histogram from candidate stream -> suffix scan ->
// threshold bin -> collect survivors -> bitonic sort -> decode.
__global__ __launch_bounds__(1024) void select_kernel(const float* __restrict__ offset,
                                                      const float* __restrict__ wh,
                                                      float* __restrict__ out){
    const int b = blockIdx.x;
    __shared__ int hist[NB1];
    __shared__ int suf[NB1];
    __shared__ unsigned long long cand[SCAP];
    __shared__ int pcnts[CN];
    __shared__ int sB1, sCol;

    const int tid = threadIdx.x;
    hist[tid] = 0; hist[tid + 1024] = 0;
    if (tid < CN){ int c = g_pcnt[b*CN + tid]; pcnts[tid] = (c > PCAP) ? PCAP : c; }
    if (tid == 0){ sCol = 0; sB1 = 0; }
    __syncthreads();

    // Pass 1: per-batch value histogram over all plane candidate slices
    for (int p = 0; p < CN; ++p){
        const unsigned long long* src = g_cand[b*CN + p];
        const int cnt = pcnts[p];
        for (int i = tid; i < cnt; i += 1024){
            float v = __uint_as_float((unsigned)(src[i] >> 32));
            atomicAdd(&hist[bin1f(v)], 1);
        }
    }
    __syncthreads();

    // Parallel suffix sum (Hillis-Steele, ping-pong)
    int* A = hist; int* B = suf;
    for (int off = 1; off < NB1; off <<= 1){
        for (int i = tid; i < NB1; i += 1024)
            B[i] = A[i] + ((i + off < NB1) ? A[i + off] : 0);
        __syncthreads();
        int* t = A; A = B; B = t;
    }
    // b1 = largest bin with suffix count >= TOPK (unique since A nonincreasing)
    for (int i = tid; i < NB1; i += 1024){
        if (A[i] >= TOPK && (i == NB1-1 || A[i+1] < TOPK)) sB1 = i;
    }
    __syncthreads();
    const int b1 = sB1;

    // Pass 2: collect survivors (bin >= b1)
    for (int p = 0; p < CN; ++p){
        const unsigned long long* src = g_cand[b*CN + p];
        const int cnt = pcnts[p];
        for (int i = tid; i < cnt; i += 1024){
            unsigned long long kk = src[i];
            float v = __uint_as_float((unsigned)(kk >> 32));
            if (bin1f(v) >= b1){
                int pos = atomicAdd(&sCol, 1);
                if (pos < SCAP) cand[pos] = kk;
            }
        }
    }
    __syncthreads();
    const int m = (sCol > SCAP) ? SCAP : sCol;
    for (int i = tid; i < SCAP; i += 1024) if (i >= m) cand[i] = 0ull;
    __syncthreads();

    // Bitonic sort 2048, descending (valbits desc, then ~idx desc == idx asc)
    for (int k = 2; k <= SCAP; k <<= 1){
        for (int j = k >> 1; j > 0; j >>= 1){
            #pragma unroll
            for (int t = 0; t < 2; ++t){
                int i = tid + t*1024;
                int ixj = i ^ j;
                if (ixj > i){
                    unsigned long long a = cand[i], c = cand[ixj];
                    bool desc = ((i & k) == 0);
                    if (desc ? (a < c) : (a > c)){ cand[i] = c; cand[ixj] = a; }
                }
            }
            __syncthreads();
        }
    }

    if (tid < TOPK){
        unsigned long long kk = cand[tid];
        unsigned vb = (unsigned)(kk >> 32);
        int idx = (int)(~(unsigned)kk);
        float score = __uint_as_float(vb);
        int chn = idx / HWN;
        int spatial = idx - chn*HWN;
        int ys = spatial >> 7, xs = spatial & (WN-1);
        const float* offb = offset + (size_t)b * 2 * HWN;
        const float* whb  = wh     + (size_t)b * 2 * HWN;
        float ox = offb[spatial], oy = offb[HWN + spatial];
        float ww = whb[spatial],  hh = whb[HWN + spatial];
        float cx = (float)xs + ox, cy = (float)ys + oy;
        float hw2 = ww * 0.5f, hh2 = hh * 0.5f;

        float* out_ids = out;                 // (B,100,1)
        float* out_sc  = out + BN*TOPK;       // (B,100,1)
        float* out_bb  = out + 2*BN*TOPK;     // (B,100,4)
        out_ids[b*TOPK + tid] = (float)chn;
        out_sc [b*TOPK + tid] = score;
        float* bbp = out_bb + (size_t)(b*TOPK + tid)*4;
        bbp[0] = (cx - hw2)*4.0f;
        bbp[1] = (cy - hh2)*4.0f;
        bbp[2] = (cx + hw2)*4.0f;
        bbp[3] = (cy + hh2)*4.0f;
    }
}

extern "C" void kernel_launch(void* const* d_in, const int* in_sizes, int n_in,
                              void* d_out, int out_size){
    const float* hm     = (const float*)d_in[0];
    const float* offset = (const float*)d_in[1];
    const float* wh     = (const float*)d_in[2];
    float* out = (float*)d_out;

    cudaFuncSetAttribute(nms_kernel, cudaFuncAttributeMaxDynamicSharedMemorySize,
                         HWN * (int)sizeof(float));

    nms_kernel<<<NPLANES, 256, HWN * sizeof(float)>>>(hm);
    select_kernel<<<BN, 1024>>>(offset, wh, out);
}